// round 1
// baseline (speedup 1.0000x reference)
#include <cuda_runtime.h>
#include <cuda_bf16.h>
#include <math.h>

#define S_LEN 4096
#define HDIM  2048
#define NHEAD 16
#define HD    128
#define QKVC  (3*HDIM)

#define BQ  64
#define BKV 64
#define PSS 68   // padded stride for P tile (conflict-free exp pass)

// Scratch (no allocations allowed): qkv = [S, 3*H], attn = [S, H]
__device__ float g_qkv[(size_t)S_LEN * QKVC];
__device__ float g_attn[(size_t)S_LEN * HDIM];

// ---------------------------------------------------------------------------
// SGEMM NT: C[M,N] = A[M,K] @ B[N,K]^T. M,N multiples of 128; K multiple of 8.
// 128x128 tile, BK=8, 256 threads, 8x8 per-thread microtile (split 4+4 for
// conflict-free float4 smem reads).
// ---------------------------------------------------------------------------
__global__ __launch_bounds__(256, 2)
void sgemm_nt(const float* __restrict__ A, const float* __restrict__ B,
              float* __restrict__ C, int M, int N, int K)
{
    __shared__ float As[8][128];
    __shared__ float Bs[8][128];

    const int tid = threadIdx.x;
    const int tx = tid & 15;
    const int ty = tid >> 4;
    const int bm = blockIdx.y * 128;
    const int bn = blockIdx.x * 128;

    const int lr = tid >> 1;           // 0..127: tile row
    const int lc = (tid & 1) << 2;     // 0 or 4: k offset
    const float* Ap = A + (size_t)(bm + lr) * K + lc;
    const float* Bp = B + (size_t)(bn + lr) * K + lc;

    float c[8][8];
    #pragma unroll
    for (int i = 0; i < 8; i++)
        #pragma unroll
        for (int j = 0; j < 8; j++) c[i][j] = 0.f;

    for (int k0 = 0; k0 < K; k0 += 8) {
        float4 av = *(const float4*)(Ap + k0);
        float4 bv = *(const float4*)(Bp + k0);
        As[lc+0][lr] = av.x; As[lc+1][lr] = av.y;
        As[lc+2][lr] = av.z; As[lc+3][lr] = av.w;
        Bs[lc+0][lr] = bv.x; Bs[lc+1][lr] = bv.y;
        Bs[lc+2][lr] = bv.z; Bs[lc+3][lr] = bv.w;
        __syncthreads();

        #pragma unroll
        for (int k = 0; k < 8; k++) {
            float a[8], b[8];
            *(float4*)&a[0] = *(const float4*)&As[k][ty << 2];
            *(float4*)&a[4] = *(const float4*)&As[k][64 + (ty << 2)];
            *(float4*)&b[0] = *(const float4*)&Bs[k][tx << 2];
            *(float4*)&b[4] = *(const float4*)&Bs[k][64 + (tx << 2)];
            #pragma unroll
            for (int i = 0; i < 8; i++)
                #pragma unroll
                for (int j = 0; j < 8; j++)
                    c[i][j] = fmaf(a[i], b[j], c[i][j]);
        }
        __syncthreads();
    }

    #pragma unroll
    for (int i = 0; i < 8; i++) {
        int m = bm + ((i < 4) ? (ty*4 + i) : (64 + ty*4 + (i - 4)));
        float* Crow = C + (size_t)m * N + bn;
        *(float4*)&Crow[tx*4]      = make_float4(c[i][0], c[i][1], c[i][2], c[i][3]);
        *(float4*)&Crow[64 + tx*4] = make_float4(c[i][4], c[i][5], c[i][6], c[i][7]);
    }
}

// ---------------------------------------------------------------------------
// Flash attention: one block = 64 queries x 1 head. Streams 64-key tiles with
// online softmax. Q/K stored d-major in smem with rotation swizzle
// (rot = d & 60) so the transpose store is <=4-way conflicted and the
// micro-GEMM reads stay vectorized + conflict-free.
// ---------------------------------------------------------------------------
__global__ __launch_bounds__(256)
void flash_attn(const float* __restrict__ qkv, float* __restrict__ attn)
{
    extern __shared__ float sm[];
    float* Qs   = sm;                    // [HD][BQ] swizzled   (32 KB)
    float* Ks   = Qs + HD*BQ;            // [HD][BKV] swizzled  (32 KB)
    float* Vs   = Ks + HD*BKV;           // [BKV][HD] natural   (32 KB)
    float* Ps   = Vs + BKV*HD;           // [BQ][PSS]           (17 KB)
    float* mrow = Ps + BQ*PSS;           // [BQ]
    float* arow = mrow + BQ;             // [BQ]
    float* lrow = arow + BQ;             // [BQ]
    float* psum = lrow + BQ;             // [BQ*4]

    const int tid = threadIdx.x;
    const int tx = tid & 15;
    const int ty = tid >> 4;
    const int h  = blockIdx.y;
    const int q0 = blockIdx.x * BQ;
    const float qsc = 0.08838834764831845f;  // 1/sqrt(128)

    // ---- load Q tile (scaled), transposed to [d][i] with swizzle ----
    for (int idx = tid; idx < BQ*HD/4; idx += 256) {
        int i  = idx >> 5;            // query row 0..63
        int d4 = (idx & 31) << 2;     // d 0..124 step 4
        float4 v = *(const float4*)&qkv[(size_t)(q0 + i)*QKVC + h*HD + d4];
        int rot = d4 & 60;            // same for d4..d4+3
        int jj  = (i + rot) & 63;
        Qs[(d4+0)*BQ + jj] = v.x * qsc;
        Qs[(d4+1)*BQ + jj] = v.y * qsc;
        Qs[(d4+2)*BQ + jj] = v.z * qsc;
        Qs[(d4+3)*BQ + jj] = v.w * qsc;
    }
    if (tid < BQ) { mrow[tid] = -INFINITY; lrow[tid] = 0.f; }

    float acc[4][8];
    #pragma unroll
    for (int i = 0; i < 4; i++)
        #pragma unroll
        for (int j = 0; j < 8; j++) acc[i][j] = 0.f;

    const int ty4 = ty << 2;
    const int tx4 = tx << 2;

    for (int kv0 = 0; kv0 < S_LEN; kv0 += BKV) {
        __syncthreads();  // previous iteration's PV reads of Ks/Vs/Ps done

        // ---- load K (transposed+swizzled) and V (natural) ----
        for (int idx = tid; idx < BKV*HD/4; idx += 256) {
            int j  = idx >> 5;
            int d4 = (idx & 31) << 2;
            const float* base = &qkv[(size_t)(kv0 + j)*QKVC + h*HD + d4];
            float4 kv4 = *(const float4*)(base + HDIM);
            float4 vv  = *(const float4*)(base + 2*HDIM);
            int rot = d4 & 60;
            int jj  = (j + rot) & 63;
            Ks[(d4+0)*BKV + jj] = kv4.x;
            Ks[(d4+1)*BKV + jj] = kv4.y;
            Ks[(d4+2)*BKV + jj] = kv4.z;
            Ks[(d4+3)*BKV + jj] = kv4.w;
            *(float4*)&Vs[j*HD + d4] = vv;
        }
        __syncthreads();

        // ---- S tile: s[i][j] for rows ty4+i, cols tx4+j ----
        float s[4][4];
        #pragma unroll
        for (int i = 0; i < 4; i++)
            #pragma unroll
            for (int j = 0; j < 4; j++) s[i][j] = 0.f;

        #pragma unroll 4
        for (int d = 0; d < HD; d++) {
            int rot = d & 60;
            float a[4], b[4];
            *(float4*)a = *(const float4*)&Qs[d*BQ  + ((ty4 + rot) & 63)];
            *(float4*)b = *(const float4*)&Ks[d*BKV + ((tx4 + rot) & 63)];
            #pragma unroll
            for (int i = 0; i < 4; i++)
                #pragma unroll
                for (int j = 0; j < 4; j++)
                    s[i][j] = fmaf(a[i], b[j], s[i][j]);
        }
        #pragma unroll
        for (int i = 0; i < 4; i++)
            *(float4*)&Ps[(ty4 + i)*PSS + tx4] =
                make_float4(s[i][0], s[i][1], s[i][2], s[i][3]);
        __syncthreads();

        // ---- row max + alpha (one thread per query row) ----
        if (tid < BQ) {
            float mo = mrow[tid];
            float mx = mo;
            const float4* row = (const float4*)&Ps[tid*PSS];
            #pragma unroll
            for (int u = 0; u < 16; u++) {
                float4 v = row[u];
                mx = fmaxf(mx, fmaxf(fmaxf(v.x, v.y), fmaxf(v.z, v.w)));
            }
            mrow[tid] = mx;
            arow[tid] = __expf(mo - mx);
        }
        __syncthreads();

        // ---- exp in place + partial sums (conflict-free stride-4 walk) ----
        {
            int r  = tid >> 2;
            int c0 = tid & 3;
            float mx = mrow[r];
            float* row = &Ps[r*PSS];
            float ssum = 0.f;
            #pragma unroll
            for (int u = 0; u < 16; u++) {
                int j = c0 + (u << 2);
                float p = __expf(row[j] - mx);
                row[j] = p;
                ssum += p;
            }
            psum[(r << 2) + c0] = ssum;
        }
        __syncthreads();

        if (tid < BQ)
            lrow[tid] = lrow[tid]*arow[tid]
                      + psum[tid*4+0] + psum[tid*4+1] + psum[tid*4+2] + psum[tid*4+3];

        // ---- rescale accumulator, then O += P @ V ----
        float al[4];
        #pragma unroll
        for (int i = 0; i < 4; i++) al[i] = arow[ty4 + i];
        #pragma unroll
        for (int i = 0; i < 4; i++)
            #pragma unroll
            for (int j = 0; j < 8; j++) acc[i][j] *= al[i];

        #pragma unroll 2
        for (int kj = 0; kj < BKV; kj++) {
            float a[4];
            a[0] = Ps[(ty4+0)*PSS + kj];
            a[1] = Ps[(ty4+1)*PSS + kj];
            a[2] = Ps[(ty4+2)*PSS + kj];
            a[3] = Ps[(ty4+3)*PSS + kj];
            float b[8];
            *(float4*)&b[0] = *(const float4*)&Vs[kj*HD + tx4];
            *(float4*)&b[4] = *(const float4*)&Vs[kj*HD + 64 + tx4];
            #pragma unroll
            for (int i = 0; i < 4; i++)
                #pragma unroll
                for (int j = 0; j < 8; j++)
                    acc[i][j] = fmaf(a[i], b[j], acc[i][j]);
        }
    }
    __syncthreads();  // lrow final values visible to all

    // ---- normalize + write [S, H] layout ----
    #pragma unroll
    for (int i = 0; i < 4; i++) {
        int r = ty4 + i;
        float inv = 1.f / (lrow[r] + 1e-8f);
        float* orow = &attn[(size_t)(q0 + r)*HDIM + h*HD];
        *(float4*)&orow[tx4]      = make_float4(acc[i][0]*inv, acc[i][1]*inv,
                                                acc[i][2]*inv, acc[i][3]*inv);
        *(float4*)&orow[64 + tx4] = make_float4(acc[i][4]*inv, acc[i][5]*inv,
                                                acc[i][6]*inv, acc[i][7]*inv);
    }
}

// ---------------------------------------------------------------------------
// Launch
// ---------------------------------------------------------------------------
static const int FLASH_SMEM = (HD*BQ + HD*BKV + BKV*HD + BQ*PSS + 3*BQ + 4*BQ) * 4;

extern "C" void kernel_launch(void* const* d_in, const int* in_sizes, int n_in,
                              void* d_out, int out_size)
{
    // Identify inputs by unique element counts (robust to ordering).
    const float *x = nullptr, *wqkv = nullptr, *wout = nullptr;
    for (int i = 0; i < n_in; i++) {
        if      (in_sizes[i] == S_LEN*HDIM) x    = (const float*)d_in[i];
        else if (in_sizes[i] == QKVC*HDIM)  wqkv = (const float*)d_in[i];
        else if (in_sizes[i] == HDIM*HDIM)  wout = (const float*)d_in[i];
    }
    float* out = (float*)d_out;

    float *qkv, *attn;
    cudaGetSymbolAddress((void**)&qkv,  g_qkv);
    cudaGetSymbolAddress((void**)&attn, g_attn);

    cudaFuncSetAttribute(flash_attn, cudaFuncAttributeMaxDynamicSharedMemorySize,
                         FLASH_SMEM);

    // 1) QKV projection: [S,3H] = X[S,H] @ Wqkv[3H,H]^T
    sgemm_nt<<<dim3(QKVC/128, S_LEN/128), 256>>>(x, wqkv, qkv, S_LEN, QKVC, HDIM);

    // 2) Attention per head, flash streaming
    flash_attn<<<dim3(S_LEN/BQ, NHEAD), 256, FLASH_SMEM>>>(qkv, attn);

    // 3) Output projection: [S,H] = A[S,H] @ Wout[H,H]^T
    sgemm_nt<<<dim3(HDIM/128, S_LEN/128), 256>>>(attn, wout, out, S_LEN, HDIM, HDIM);
}

// round 4
// speedup vs baseline: 3.9450x; 3.9450x over previous
#include <cuda_runtime.h>
#include <cuda_bf16.h>
#include <cstdint>
#include <math.h>

#define S_LEN 4096
#define HDIM  2048
#define NHEAD 16
#define HD    128
#define QKVC  (3*HDIM)

// Q pre-scale: 1/sqrt(128) * log2(e)  (softmax done in exp2 domain)
#define QSCL (0.08838834764831845f * 1.4426950408889634f)

// ---------------- scratch (static; no allocations allowed) ----------------
__device__ __nv_bfloat16 g_xh[(size_t)S_LEN * HDIM],  g_xl[(size_t)S_LEN * HDIM];
__device__ __nv_bfloat16 g_wqh[(size_t)QKVC * HDIM],  g_wql[(size_t)QKVC * HDIM];
__device__ __nv_bfloat16 g_woh[(size_t)HDIM * HDIM],  g_wol[(size_t)HDIM * HDIM];
__device__ __nv_bfloat16 g_qh[(size_t)NHEAD*S_LEN*HD], g_ql[(size_t)NHEAD*S_LEN*HD];
__device__ __nv_bfloat16 g_kh[(size_t)NHEAD*S_LEN*HD], g_kl[(size_t)NHEAD*S_LEN*HD];
__device__ __nv_bfloat16 g_vh[(size_t)NHEAD*S_LEN*HD], g_vl[(size_t)NHEAD*S_LEN*HD];
__device__ __nv_bfloat16 g_ah[(size_t)S_LEN * HDIM],  g_al[(size_t)S_LEN * HDIM];
__device__ int g_probe_sink;

// ---------------- asm helpers (base sm_100 legal) ----------------
__device__ __forceinline__ uint32_t smem_u32(const void* p) {
    uint32_t a;
    asm("{ .reg .u64 t; cvta.to.shared.u64 t, %1; cvt.u32.u64 %0, t; }" : "=r"(a) : "l"(p));
    return a;
}
__device__ __forceinline__ void cp_async16(uint32_t dst, const void* src) {
    asm volatile("cp.async.cg.shared.global [%0], [%1], 16;"
                 :: "r"(dst), "l"(__cvta_generic_to_global(src)));
}
#define CP_COMMIT() asm volatile("cp.async.commit_group;" ::: "memory")
#define CP_WAIT(n)  asm volatile("cp.async.wait_group %0;" :: "n"(n) : "memory")

__device__ __forceinline__ void ldsm_x4(uint32_t* r, uint32_t a) {
    asm volatile("ldmatrix.sync.aligned.m8n8.x4.shared.b16 {%0,%1,%2,%3}, [%4];"
                 : "=r"(r[0]), "=r"(r[1]), "=r"(r[2]), "=r"(r[3]) : "r"(a));
}
__device__ __forceinline__ void ldsm_x4_t(uint32_t* r, uint32_t a) {
    asm volatile("ldmatrix.sync.aligned.m8n8.x4.trans.shared.b16 {%0,%1,%2,%3}, [%4];"
                 : "=r"(r[0]), "=r"(r[1]), "=r"(r[2]), "=r"(r[3]) : "r"(a));
}
__device__ __forceinline__ void mma_bf16(float* d, const uint32_t* a, const uint32_t* b) {
    asm volatile("mma.sync.aligned.m16n8k16.row.col.f32.bf16.bf16.f32 "
                 "{%0,%1,%2,%3}, {%4,%5,%6,%7}, {%8,%9}, {%0,%1,%2,%3};"
                 : "+f"(d[0]), "+f"(d[1]), "+f"(d[2]), "+f"(d[3])
                 : "r"(a[0]), "r"(a[1]), "r"(a[2]), "r"(a[3]), "r"(b[0]), "r"(b[1]));
}
__device__ __forceinline__ float ex2f(float x) {
    float y; asm("ex2.approx.ftz.f32 %0, %1;" : "=f"(y) : "f"(x)); return y;
}
__device__ __forceinline__ uint32_t pack_bf16(float f0, float f1) {
    return (uint32_t)__bfloat16_as_ushort(__float2bfloat16(f0))
         | ((uint32_t)__bfloat16_as_ushort(__float2bfloat16(f1)) << 16);
}
__device__ __forceinline__ void st_split2(__nv_bfloat16* dh, __nv_bfloat16* dl,
                                          size_t idx, float f0, float f1) {
    __nv_bfloat16 h0 = __float2bfloat16(f0), h1 = __float2bfloat16(f1);
    *(uint32_t*)(dh + idx) = (uint32_t)__bfloat16_as_ushort(h0)
                           | ((uint32_t)__bfloat16_as_ushort(h1) << 16);
    *(uint32_t*)(dl + idx) = pack_bf16(f0 - __bfloat162float(h0),
                                       f1 - __bfloat162float(h1));
}
__device__ __forceinline__ void pack_split(float f0, float f1, uint32_t& hi, uint32_t& lo) {
    __nv_bfloat16 h0 = __float2bfloat16(f0), h1 = __float2bfloat16(f1);
    hi = (uint32_t)__bfloat16_as_ushort(h0) | ((uint32_t)__bfloat16_as_ushort(h1) << 16);
    lo = pack_bf16(f0 - __bfloat162float(h0), f1 - __bfloat162float(h1));
}

// ---------------------------------------------------------------------------
// fp32 -> (bf16 hi, bf16 lo) split, n4 = n/4
// ---------------------------------------------------------------------------
__global__ void split_f32_kernel(const float* __restrict__ in,
                                 __nv_bfloat16* __restrict__ hi,
                                 __nv_bfloat16* __restrict__ lo, int n4)
{
    int i = blockIdx.x * blockDim.x + threadIdx.x;
    if (i >= n4) return;
    float4 v = ((const float4*)in)[i];
    float f[4] = {v.x, v.y, v.z, v.w};
    uint32_t hp[2], lp[2];
    #pragma unroll
    for (int q = 0; q < 2; q++) {
        __nv_bfloat16 h0 = __float2bfloat16(f[2*q]);
        __nv_bfloat16 h1 = __float2bfloat16(f[2*q+1]);
        hp[q] = (uint32_t)__bfloat16_as_ushort(h0) | ((uint32_t)__bfloat16_as_ushort(h1) << 16);
        lp[q] = pack_bf16(f[2*q]   - __bfloat162float(h0),
                          f[2*q+1] - __bfloat162float(h1));
    }
    ((uint2*)hi)[i] = make_uint2(hp[0], hp[1]);
    ((uint2*)lo)[i] = make_uint2(lp[0], lp[1]);
}

__global__ void probe_kernel() { if (threadIdx.x == 0) g_probe_sink = 1; }

// ---------------------------------------------------------------------------
// Split-bf16 HMMA GEMM: C[M,N] = A[M,K] @ B[N,K]^T, fp32-accurate via 3 MMAs.
// CTA 128x128, BK=64 (128B swizzled rows), cp.async double buffer, 8 warps.
// MODE 0: C fp32 row-major.  MODE 1: QKV split epilogue -> g_q/k/v hi+lo.
// ---------------------------------------------------------------------------
#define GSTG (64*1024)

__device__ __forceinline__ void gemm_load_stage(
    uint32_t sbase, const __nv_bfloat16* Ah, const __nv_bfloat16* Al,
    const __nv_bfloat16* Bh, const __nv_bfloat16* Bl,
    int bm, int bn, int K, int k0, int tid)
{
    #pragma unroll
    for (int i = 0; i < 16; i++) {
        int id   = tid + i * 256;          // 0..4095
        int tsel = id >> 10;
        int rem  = id & 1023;
        int r    = rem >> 3;
        int ci   = rem & 7;
        const __nv_bfloat16* g = (tsel == 0) ? Ah : (tsel == 1) ? Al : (tsel == 2) ? Bh : Bl;
        int grow = ((tsel < 2) ? bm : bn) + r;
        const __nv_bfloat16* src = g + (size_t)grow * K + k0 + ci * 8;
        uint32_t dst = sbase + tsel * 16384 + r * 128 + ((ci * 16) ^ ((r & 7) << 4));
        cp_async16(dst, src);
    }
}

template<int MODE>
__global__ __launch_bounds__(256, 1)
void gemm_mma(const __nv_bfloat16* __restrict__ Ah, const __nv_bfloat16* __restrict__ Al,
              const __nv_bfloat16* __restrict__ Bh, const __nv_bfloat16* __restrict__ Bl,
              float* __restrict__ Cf,
              __nv_bfloat16* __restrict__ qh, __nv_bfloat16* __restrict__ ql,
              __nv_bfloat16* __restrict__ kh, __nv_bfloat16* __restrict__ kl,
              __nv_bfloat16* __restrict__ vh, __nv_bfloat16* __restrict__ vl,
              int M, int N, int K)
{
    extern __shared__ __align__(1024) char smem[];
    const uint32_t sb = smem_u32(smem);
    const int tid  = threadIdx.x;
    const int wid  = tid >> 5;
    const int lane = tid & 31;
    const int bm = blockIdx.y * 128;
    const int bn = blockIdx.x * 128;
    const int wm = (wid >> 1) * 32;
    const int wn = (wid & 1) * 64;

    float acc[2][8][4];
    #pragma unroll
    for (int a = 0; a < 2; a++)
        #pragma unroll
        for (int b = 0; b < 8; b++)
            #pragma unroll
            for (int c = 0; c < 4; c++) acc[a][b][c] = 0.f;

    const int NC = K / 64;
    gemm_load_stage(sb, Ah, Al, Bh, Bl, bm, bn, K, 0, tid);
    CP_COMMIT();

    for (int c = 0; c < NC; c++) {
        __syncthreads();
        if (c + 1 < NC) {
            gemm_load_stage(sb + ((c + 1) & 1) * GSTG, Ah, Al, Bh, Bl, bm, bn, K, (c + 1) * 64, tid);
            CP_COMMIT();
            CP_WAIT(1);
        } else {
            CP_WAIT(0);
        }
        __syncthreads();

        uint32_t sAh = sb + (c & 1) * GSTG;
        uint32_t sAl = sAh + 16384, sBh = sAh + 32768, sBl = sAh + 49152;

        #pragma unroll
        for (int ks = 0; ks < 4; ks++) {
            const int kb = ks * 32;
            uint32_t aH[2][4], aL[2][4];
            {
                int ar = lane & 15, acb = kb + (lane >> 4) * 16;
                #pragma unroll
                for (int ms = 0; ms < 2; ms++) {
                    int r = wm + ms * 16 + ar;
                    uint32_t off = r * 128 + (acb ^ ((r & 7) << 4));
                    ldsm_x4(aH[ms], sAh + off);
                    ldsm_x4(aL[ms], sAl + off);
                }
            }
            #pragma unroll
            for (int ng = 0; ng < 4; ng++) {
                int br  = wn + ng * 16 + (lane & 7) + ((lane >> 4) << 3);
                int bcb = kb + ((lane >> 3) & 1) * 16;
                uint32_t off = br * 128 + (bcb ^ ((br & 7) << 4));
                uint32_t bH[4], bL[4];
                ldsm_x4(bH, sBh + off);
                ldsm_x4(bL, sBl + off);
                #pragma unroll
                for (int ms = 0; ms < 2; ms++) {
                    mma_bf16(acc[ms][ng*2],   aH[ms], bH);
                    mma_bf16(acc[ms][ng*2],   aH[ms], bL);
                    mma_bf16(acc[ms][ng*2],   aL[ms], bH);
                    mma_bf16(acc[ms][ng*2+1], aH[ms], bH + 2);
                    mma_bf16(acc[ms][ng*2+1], aH[ms], bL + 2);
                    mma_bf16(acc[ms][ng*2+1], aL[ms], bH + 2);
                }
            }
        }
    }

    // epilogue
    #pragma unroll
    for (int ms = 0; ms < 2; ms++) {
        #pragma unroll
        for (int b = 0; b < 8; b++) {
            int r0 = bm + wm + ms * 16 + (lane >> 2);
            int c0 = bn + wn + b * 8 + (lane & 3) * 2;
            if (MODE == 0) {
                *(float2*)&Cf[(size_t)r0 * N + c0]       = make_float2(acc[ms][b][0], acc[ms][b][1]);
                *(float2*)&Cf[(size_t)(r0 + 8) * N + c0] = make_float2(acc[ms][b][2], acc[ms][b][3]);
            } else {
                int t = c0 >> 11, hh = (c0 >> 7) & 15, d = c0 & 127;
                __nv_bfloat16* dh = (t == 0) ? qh : (t == 1) ? kh : vh;
                __nv_bfloat16* dl = (t == 0) ? ql : (t == 1) ? kl : vl;
                float sc = (t == 0) ? QSCL : 1.f;
                size_t i0 = ((size_t)hh * S_LEN + r0) * HD + d;
                st_split2(dh, dl, i0,            acc[ms][b][0] * sc, acc[ms][b][1] * sc);
                st_split2(dh, dl, i0 + 8 * HD,   acc[ms][b][2] * sc, acc[ms][b][3] * sc);
            }
        }
    }
}

// ---------------------------------------------------------------------------
// FMHA on HMMA: CTA = 128 queries x 1 head, 8 warps (16 rows each).
// Split-bf16 QK^T and PV (3 MMAs each). In-register online softmax (exp2).
// smem: Qh|Ql (64KB) + 2 stages of Kh|Kl|Vh|Vl (64KB each) = 192KB.
// ---------------------------------------------------------------------------
#define FSTG (64*1024)
#define FSMEM (192*1024)
#define NTILE (S_LEN/64)

__device__ __forceinline__ void fmha_load_kv(
    uint32_t sbase, const __nv_bfloat16* kh, const __nv_bfloat16* kl,
    const __nv_bfloat16* vh, const __nv_bfloat16* vl,
    size_t head_off, int j0, int tid)
{
    #pragma unroll
    for (int i = 0; i < 16; i++) {
        int id   = tid + i * 256;           // 0..4095
        int tsel = id >> 10;
        int rem  = id & 1023;
        int r    = rem >> 4;                // kv row 0..63
        int ci   = rem & 15;
        const __nv_bfloat16* g = (tsel == 0) ? kh : (tsel == 1) ? kl : (tsel == 2) ? vh : vl;
        const __nv_bfloat16* src = g + head_off + (size_t)(j0 + r) * HD + ci * 8;
        uint32_t dst = sbase + tsel * 16384 + r * 256 + ((ci * 16) ^ ((r & 7) << 4));
        cp_async16(dst, src);
    }
}

__global__ __launch_bounds__(256, 1)
void fmha_mma(const __nv_bfloat16* __restrict__ qh, const __nv_bfloat16* __restrict__ ql,
              const __nv_bfloat16* __restrict__ kh, const __nv_bfloat16* __restrict__ kl,
              const __nv_bfloat16* __restrict__ vh, const __nv_bfloat16* __restrict__ vl,
              __nv_bfloat16* __restrict__ ah, __nv_bfloat16* __restrict__ al)
{
    extern __shared__ __align__(1024) char smem[];
    const uint32_t sb = smem_u32(smem);
    const int tid  = threadIdx.x;
    const int wid  = tid >> 5;
    const int lane = tid & 31;
    const int h  = blockIdx.y;
    const int q0 = blockIdx.x * 128;
    const size_t hoff = (size_t)h * S_LEN * HD;

    // ---- load Q tiles (hi/lo) ----
    #pragma unroll
    for (int i = 0; i < 16; i++) {
        int id   = tid + i * 256;           // 0..4095
        int tsel = id >> 11;
        int rem  = id & 2047;
        int r    = rem >> 4;                // q row 0..127
        int ci   = rem & 15;
        const __nv_bfloat16* g = tsel ? ql : qh;
        const __nv_bfloat16* src = g + hoff + (size_t)(q0 + r) * HD + ci * 8;
        uint32_t dst = sb + tsel * 32768 + r * 256 + ((ci * 16) ^ ((r & 7) << 4));
        cp_async16(dst, src);
    }
    fmha_load_kv(sb + 65536, kh, kl, vh, vl, hoff, 0, tid);
    CP_COMMIT();

    float oacc[16][4];
    #pragma unroll
    for (int b = 0; b < 16; b++)
        #pragma unroll
        for (int c = 0; c < 4; c++) oacc[b][c] = 0.f;
    float m0 = -1e30f, m1 = -1e30f, l0 = 0.f, l1 = 0.f;

    #pragma unroll 1
    for (int t = 0; t < NTILE; t++) {
        __syncthreads();
        if (t + 1 < NTILE) {
            fmha_load_kv(sb + 65536 + ((t + 1) & 1) * FSTG, kh, kl, vh, vl,
                         hoff, (t + 1) * 64, tid);
            CP_COMMIT();
            CP_WAIT(1);
        } else {
            CP_WAIT(0);
        }
        __syncthreads();

        const uint32_t sQh = sb, sQl = sb + 32768;
        const uint32_t sK  = sb + 65536 + (t & 1) * FSTG;
        const uint32_t sKh = sK, sKl = sK + 16384, sVh = sK + 32768, sVl = sK + 49152;

        // ---- S = Q K^T (scaled), 64 kv cols ----
        float sacc[8][4];
        #pragma unroll
        for (int b = 0; b < 8; b++)
            #pragma unroll
            for (int c = 0; c < 4; c++) sacc[b][c] = 0.f;

        #pragma unroll
        for (int ks = 0; ks < 8; ks++) {
            const int kb = ks * 32;
            uint32_t aH[4], aL[4];
            {
                int r = wid * 16 + (lane & 15);
                int cb = kb + (lane >> 4) * 16;
                uint32_t off = r * 256 + (cb ^ ((r & 7) << 4));
                ldsm_x4(aH, sQh + off);
                ldsm_x4(aL, sQl + off);
            }
            #pragma unroll
            for (int ng = 0; ng < 4; ng++) {
                int br  = ng * 16 + (lane & 7) + ((lane >> 4) << 3);
                int bcb = kb + ((lane >> 3) & 1) * 16;
                uint32_t off = br * 256 + (bcb ^ ((br & 7) << 4));
                uint32_t bH[4], bL[4];
                ldsm_x4(bH, sKh + off);
                ldsm_x4(bL, sKl + off);
                mma_bf16(sacc[ng*2],   aH, bH);
                mma_bf16(sacc[ng*2],   aH, bL);
                mma_bf16(sacc[ng*2],   aL, bH);
                mma_bf16(sacc[ng*2+1], aH, bH + 2);
                mma_bf16(sacc[ng*2+1], aH, bL + 2);
                mma_bf16(sacc[ng*2+1], aL, bH + 2);
            }
        }

        // ---- online softmax (rows r0=lane/4, r1=lane/4+8 of warp strip) ----
        float tm0 = -1e30f, tm1 = -1e30f;
        #pragma unroll
        for (int b = 0; b < 8; b++) {
            tm0 = fmaxf(tm0, fmaxf(sacc[b][0], sacc[b][1]));
            tm1 = fmaxf(tm1, fmaxf(sacc[b][2], sacc[b][3]));
        }
        tm0 = fmaxf(tm0, __shfl_xor_sync(0xffffffffu, tm0, 1));
        tm0 = fmaxf(tm0, __shfl_xor_sync(0xffffffffu, tm0, 2));
        tm1 = fmaxf(tm1, __shfl_xor_sync(0xffffffffu, tm1, 1));
        tm1 = fmaxf(tm1, __shfl_xor_sync(0xffffffffu, tm1, 2));
        float mn0 = fmaxf(m0, tm0), mn1 = fmaxf(m1, tm1);
        float al0 = ex2f(m0 - mn0), al1 = ex2f(m1 - mn1);
        m0 = mn0; m1 = mn1;

        float rs0 = 0.f, rs1 = 0.f;
        #pragma unroll
        for (int b = 0; b < 8; b++) {
            sacc[b][0] = ex2f(sacc[b][0] - mn0);
            sacc[b][1] = ex2f(sacc[b][1] - mn0);
            sacc[b][2] = ex2f(sacc[b][2] - mn1);
            sacc[b][3] = ex2f(sacc[b][3] - mn1);
            rs0 += sacc[b][0] + sacc[b][1];
            rs1 += sacc[b][2] + sacc[b][3];
        }
        rs0 += __shfl_xor_sync(0xffffffffu, rs0, 1);
        rs0 += __shfl_xor_sync(0xffffffffu, rs0, 2);
        rs1 += __shfl_xor_sync(0xffffffffu, rs1, 1);
        rs1 += __shfl_xor_sync(0xffffffffu, rs1, 2);
        l0 = l0 * al0 + rs0;
        l1 = l1 * al1 + rs1;

        #pragma unroll
        for (int b = 0; b < 16; b++) {
            oacc[b][0] *= al0; oacc[b][1] *= al0;
            oacc[b][2] *= al1; oacc[b][3] *= al1;
        }

        // ---- repack P (c-frag -> a-frag, in-lane), split hi/lo ----
        uint32_t pH[4][4], pL[4][4];
        #pragma unroll
        for (int k2 = 0; k2 < 4; k2++) {
            pack_split(sacc[2*k2][0],   sacc[2*k2][1],   pH[k2][0], pL[k2][0]);
            pack_split(sacc[2*k2][2],   sacc[2*k2][3],   pH[k2][1], pL[k2][1]);
            pack_split(sacc[2*k2+1][0], sacc[2*k2+1][1], pH[k2][2], pL[k2][2]);
            pack_split(sacc[2*k2+1][2], sacc[2*k2+1][3], pH[k2][3], pL[k2][3]);
        }

        // ---- O += P V  (V natural [j][d]; B-frags via ldmatrix.trans) ----
        #pragma unroll
        for (int k2 = 0; k2 < 4; k2++) {
            #pragma unroll
            for (int dg = 0; dg < 8; dg++) {
                int vr  = k2 * 16 + (lane & 7) + ((lane >> 3) & 1) * 8;
                int vcb = dg * 32 + (lane >> 4) * 16;
                uint32_t off = vr * 256 + (vcb ^ ((vr & 7) << 4));
                uint32_t vH[4], vL[4];
                ldsm_x4_t(vH, sVh + off);
                ldsm_x4_t(vL, sVl + off);
                mma_bf16(oacc[dg*2],   pH[k2], vH);
                mma_bf16(oacc[dg*2],   pH[k2], vL);
                mma_bf16(oacc[dg*2],   pL[k2], vH);
                mma_bf16(oacc[dg*2+1], pH[k2], vH + 2);
                mma_bf16(oacc[dg*2+1], pH[k2], vL + 2);
                mma_bf16(oacc[dg*2+1], pL[k2], vH + 2);
            }
        }
    }

    // ---- normalize + split-write attention output [S][HDIM] ----
    float inv0 = 1.f / (l0 + 1e-8f);
    float inv1 = 1.f / (l1 + 1e-8f);
    int row0 = q0 + wid * 16 + (lane >> 2);
    #pragma unroll
    for (int b = 0; b < 16; b++) {
        int d0 = h * HD + b * 8 + (lane & 3) * 2;
        st_split2(ah, al, (size_t)row0 * HDIM + d0,
                  oacc[b][0] * inv0, oacc[b][1] * inv0);
        st_split2(ah, al, (size_t)(row0 + 8) * HDIM + d0,
                  oacc[b][2] * inv1, oacc[b][3] * inv1);
    }
}

// ---------------------------------------------------------------------------
extern "C" void kernel_launch(void* const* d_in, const int* in_sizes, int n_in,
                              void* d_out, int out_size)
{
    const float *x = nullptr, *wqkv = nullptr, *wout = nullptr;
    for (int i = 0; i < n_in; i++) {
        if      (in_sizes[i] == S_LEN*HDIM) x    = (const float*)d_in[i];
        else if (in_sizes[i] == QKVC*HDIM)  wqkv = (const float*)d_in[i];
        else if (in_sizes[i] == HDIM*HDIM)  wout = (const float*)d_in[i];
    }
    float* out = (float*)d_out;

    __nv_bfloat16 *xh, *xl, *wqh, *wql, *woh, *wol, *ah, *al;
    __nv_bfloat16 *qh, *ql, *kh, *kl, *vh, *vl;
    cudaGetSymbolAddress((void**)&xh,  g_xh);  cudaGetSymbolAddress((void**)&xl,  g_xl);
    cudaGetSymbolAddress((void**)&wqh, g_wqh); cudaGetSymbolAddress((void**)&wql, g_wql);
    cudaGetSymbolAddress((void**)&woh, g_woh); cudaGetSymbolAddress((void**)&wol, g_wol);
    cudaGetSymbolAddress((void**)&ah,  g_ah);  cudaGetSymbolAddress((void**)&al,  g_al);
    cudaGetSymbolAddress((void**)&qh,  g_qh);  cudaGetSymbolAddress((void**)&ql,  g_ql);
    cudaGetSymbolAddress((void**)&kh,  g_kh);  cudaGetSymbolAddress((void**)&kl,  g_kl);
    cudaGetSymbolAddress((void**)&vh,  g_vh);  cudaGetSymbolAddress((void**)&vl,  g_vl);

    cudaFuncSetAttribute(gemm_mma<0>, cudaFuncAttributeMaxDynamicSharedMemorySize, 2*GSTG);
    cudaFuncSetAttribute(gemm_mma<1>, cudaFuncAttributeMaxDynamicSharedMemorySize, 2*GSTG);
    cudaFuncSetAttribute(fmha_mma,    cudaFuncAttributeMaxDynamicSharedMemorySize, FSMEM);

    // 1-3: fp32 -> bf16 hi/lo splits
    split_f32_kernel<<<(S_LEN*HDIM/4 + 255)/256, 256>>>(x,    xh,  xl,  S_LEN*HDIM/4);
    split_f32_kernel<<<(QKVC*HDIM/4  + 255)/256, 256>>>(wqkv, wqh, wql, QKVC*HDIM/4);
    split_f32_kernel<<<(HDIM*HDIM/4  + 255)/256, 256>>>(wout, woh, wol, HDIM*HDIM/4);

    // 4: QKV projection -> per-head split q/k/v (Q pre-scaled)
    gemm_mma<1><<<dim3(QKVC/128, S_LEN/128), 256, 2*GSTG>>>(
        xh, xl, wqh, wql, nullptr, qh, ql, kh, kl, vh, vl, S_LEN, QKVC, HDIM);

    // 5: probe (ncu -s 5 -c 1 lands on #6 = fmha)
    probe_kernel<<<1, 32>>>();

    // 6: attention
    fmha_mma<<<dim3(S_LEN/128, NHEAD), 256, FSMEM>>>(qh, ql, kh, kl, vh, vl, ah, al);

    // 7: output projection -> fp32 out
    gemm_mma<0><<<dim3(HDIM/128, S_LEN/128), 256, 2*GSTG>>>(
        ah, al, woh, wol, out, nullptr, nullptr, nullptr, nullptr, nullptr, nullptr,
        S_LEN, HDIM, HDIM);
}